// round 6
// baseline (speedup 1.0000x reference)
#include <cuda_runtime.h>
#include <cstdint>

// Fixed geometry: x_list (P=16384, N=1024, 2) float32, scale scalar.
// segn = N/4 = 256 segments/row; segment i uses points 3i..3i+3
// -> touched floats per row: [0, 1538). Load [0, 1540) as 385 float4.
#define N_POINTS        1024
#define ROW_FLOATS      (N_POINTS * 2)      // 2048
#define ROW_F4          (ROW_FLOATS / 4)    // 512 (full row in float4)
#define LOAD_F4         385                 // float4s covering touched region
#define BUF_F4          388                 // slight pad
#define SEGN            256
#define ROWS_PER_BLOCK  8
#define MAX_BLOCKS      4096

__device__ float        g_partials[MAX_BLOCKS];
__device__ unsigned int g_counter = 0;

__device__ __forceinline__ void cp16(uint32_t smem_dst, const void* gsrc)
{
    asm volatile("cp.async.cg.shared.global [%0], [%1], 16;"
                 :: "r"(smem_dst), "l"(gsrc));
}
__device__ __forceinline__ void cp_commit()
{
    asm volatile("cp.async.commit_group;" ::: "memory");
}
template <int N>
__device__ __forceinline__ void cp_wait()
{
    asm volatile("cp.async.wait_group %0;" :: "n"(N) : "memory");
}

// Crossing term for one segment given its 4 points.
__device__ __forceinline__ float seg_term(float2 p0, float2 p1, float2 p2, float2 p3)
{
    const float v1x = p1.x - p0.x, v1y = p1.y - p0.y;
    const float v2x = p2.x - p1.x, v2y = p2.y - p1.y;
    const float v3x = p3.x - p2.x, v3y = p3.y - p2.y;

    // direct = (s12 >= 0) depends only on sign of cross(v1,v2):
    // the positive norm product cannot flip the sign.
    const float c12 = v1x * v2y - v1y * v2x;
    const float c13 = v1x * v3y - v1y * v3x;

    const float n2   = (v1x * v1x + v1y * v1y) * (v3x * v3x + v3y * v3y);
    const float sina = c13 * rsqrtf(n2);

    return (c12 >= 0.0f) ? fmaxf(-sina, 0.0f) : fmaxf(sina, 0.0f);
}

__global__ void __launch_bounds__(SEGN, 8) xing_kernel(
    const float* __restrict__ x,
    const uint32_t* __restrict__ scale_raw,
    float* __restrict__ out, int P, int nblocks)
{
    __shared__ float4 buf[2][BUF_F4];

    const int t = threadIdx.x;               // segment index 0..255

    const float4* __restrict__ rowbase =
        reinterpret_cast<const float4*>(x)
        + (size_t)blockIdx.x * ROWS_PER_BLOCK * ROW_F4;

    const uint32_t s0 = (uint32_t)__cvta_generic_to_shared(&buf[0][0]);
    const uint32_t s1 = (uint32_t)__cvta_generic_to_shared(&buf[1][0]);

    // Coalesced row copy: 385 float4 with 256 threads (threads 0..128 do two).
    #define ISSUE_ROW(r, b)                                              \
        do {                                                             \
            const float4* g = rowbase + (size_t)(r) * ROW_F4;            \
            uint32_t s = (b) ? s1 : s0;                                  \
            cp16(s + t * 16u, g + t);                                    \
            if (t < LOAD_F4 - SEGN) cp16(s + (SEGN + t) * 16u, g + SEGN + t); \
            cp_commit();                                                 \
        } while (0)

    ISSUE_ROW(0, 0);

    float acc = 0.0f;
    #pragma unroll
    for (int r = 0; r < ROWS_PER_BLOCK; r++) {
        if (r + 1 < ROWS_PER_BLOCK) {
            ISSUE_ROW(r + 1, (r + 1) & 1);
            cp_wait<1>();                    // row r's group has landed
        } else {
            cp_wait<0>();
        }
        __syncthreads();                     // row r visible to all threads

        const float* row = reinterpret_cast<const float*>(buf[r & 1]);
        const float2 p0 = *reinterpret_cast<const float2*>(row + 6 * t + 0);
        const float2 p1 = *reinterpret_cast<const float2*>(row + 6 * t + 2);
        const float2 p2 = *reinterpret_cast<const float2*>(row + 6 * t + 4);
        const float2 p3 = *reinterpret_cast<const float2*>(row + 6 * t + 6);
        acc += seg_term(p0, p1, p2, p3);

        __syncthreads();                     // done reading buf[r&1] before
                                             // iter r+1 issues row r+2 into it
    }

    // ---- block reduce ----
    #pragma unroll
    for (int o = 16; o > 0; o >>= 1)
        acc += __shfl_down_sync(0xFFFFFFFFu, acc, o);

    __shared__ float s[SEGN / 32];
    __shared__ bool  isLast;
    if ((t & 31) == 0) s[t >> 5] = acc;
    __syncthreads();

    if (t == 0) {
        float bs = 0.0f;
        #pragma unroll
        for (int i = 0; i < SEGN / 32; i++) bs += s[i];
        g_partials[blockIdx.x] = bs;
        __threadfence();
        unsigned int done = atomicAdd(&g_counter, 1u);
        isLast = (done == (unsigned int)(nblocks - 1));
    }
    __syncthreads();

    // ---- last block folds the nblocks partials ----
    if (isLast) {
        float v = 0.0f;
        for (int i = t; i < nblocks; i += SEGN)
            v += __ldcg(&g_partials[i]);

        #pragma unroll
        for (int o = 16; o > 0; o >>= 1)
            v += __shfl_down_sync(0xFFFFFFFFu, v, o);
        if ((t & 31) == 0) s[t >> 5] = v;
        __syncthreads();

        if (t == 0) {
            float total = 0.0f;
            #pragma unroll
            for (int i = 0; i < SEGN / 32; i++) total += s[i];

            // Decode scale: float32 bit pattern vs integer bit pattern.
            uint32_t u = scale_raw[0];
            float    f = __uint_as_float(u);
            float    scale;
            if (fabsf(f) >= 1e-30f && fabsf(f) < 1e30f) scale = f;
            else                                        scale = (float)(int)u;

            out[0] = total * scale / ((float)SEGN * (float)P);
            // Reset counter for the next (graph-replayed) launch.
            atomicExch(&g_counter, 0u);
        }
    }
}

extern "C" void kernel_launch(void* const* d_in, const int* in_sizes, int n_in,
                              void* d_out, int out_size)
{
    const float*    x     = (const float*)d_in[0];
    const uint32_t* scale = (const uint32_t*)d_in[1];
    float*          out   = (float*)d_out;

    int P       = in_sizes[0] / ROW_FLOATS;   // 16384
    int nblocks = P / ROWS_PER_BLOCK;         // 2048

    xing_kernel<<<nblocks, SEGN>>>(x, scale, out, P, nblocks);
}

// round 7
// speedup vs baseline: 1.1152x; 1.1152x over previous
#include <cuda_runtime.h>
#include <cstdint>

// Fixed geometry: x_list (P=16384, N=1024, 2) float32, scale scalar.
// segn = N/4 = 256 segments per row; segment i uses points 3i..3i+3.
#define N_POINTS        1024
#define SEGN            256
#define ROWS_PER_BLOCK  8
#define NSLOTS          32

__device__ float        g_slots[NSLOTS];   // zero-init at load; reset each launch
__device__ unsigned int g_counter = 0;

// Crossing term for one segment given its 4 points.
__device__ __forceinline__ float seg_term(float2 p0, float2 p1, float2 p2, float2 p3)
{
    const float v1x = p1.x - p0.x, v1y = p1.y - p0.y;
    const float v2x = p2.x - p1.x, v2y = p2.y - p1.y;
    const float v3x = p3.x - p2.x, v3y = p3.y - p2.y;

    // direct = (s12 >= 0) depends only on sign of cross(v1,v2):
    // the positive norm product cannot flip the sign.
    const float c12 = v1x * v2y - v1y * v2x;
    const float c13 = v1x * v3y - v1y * v3x;

    const float n2   = (v1x * v1x + v1y * v1y) * (v3x * v3x + v3y * v3y);
    const float sina = c13 * rsqrtf(n2);

    return (c12 >= 0.0f) ? fmaxf(-sina, 0.0f) : fmaxf(sina, 0.0f);
}

__global__ void __launch_bounds__(SEGN, 8) xing_kernel(
    const float* __restrict__ x,
    const uint32_t* __restrict__ scale_raw,
    float* __restrict__ out, int P, int nblocks)
{
    const int t    = threadIdx.x;           // segment index 0..255
    const int lane = t & 31;

    // Segment t starts at point 3t within each row.
    const float2* __restrict__ base =
        reinterpret_cast<const float2*>(x)
        + (size_t)blockIdx.x * ROWS_PER_BLOCK * N_POINTS + 3 * t;

    float acc = 0.0f;

    #pragma unroll
    for (int r = 0; r < ROWS_PER_BLOCK; r++) {
        const float2* p = base + (size_t)r * N_POINTS;

        // 3 loads per segment; p3 comes from the next lane's p0.
        const float2 p0 = __ldg(p + 0);
        const float2 p1 = __ldg(p + 1);
        const float2 p2 = __ldg(p + 2);

        float2 pb = make_float2(0.0f, 0.0f);
        if (lane == 31) pb = __ldg(p + 3);   // warp-boundary segment

        float2 p3;
        p3.x = __shfl_down_sync(0xFFFFFFFFu, p0.x, 1);
        p3.y = __shfl_down_sync(0xFFFFFFFFu, p0.y, 1);
        if (lane == 31) p3 = pb;

        acc += seg_term(p0, p1, p2, p3);
    }

    // ---- block reduce ----
    #pragma unroll
    for (int o = 16; o > 0; o >>= 1)
        acc += __shfl_down_sync(0xFFFFFFFFu, acc, o);

    __shared__ float s[SEGN / 32];
    __shared__ bool  isLast;
    if (lane == 0) s[t >> 5] = acc;
    __syncthreads();

    if (t == 0) {
        float bs = 0.0f;
        #pragma unroll
        for (int i = 0; i < SEGN / 32; i++) bs += s[i];
        // Spread accumulation: 32 distinct L2 addresses, ~64 adds each
        // spread over the kernel lifetime -> negligible contention.
        atomicAdd(&g_slots[blockIdx.x & (NSLOTS - 1)], bs);
        __threadfence();
        unsigned int done = atomicAdd(&g_counter, 1u);
        isLast = (done == (unsigned int)(nblocks - 1));
    }
    __syncthreads();

    // ---- last-arriving block folds the 32 slots (single warp) ----
    if (isLast && t < NSLOTS) {
        float v = g_slots[t];
        g_slots[t] = 0.0f;                   // reset for next graph replay

        #pragma unroll
        for (int o = NSLOTS / 2; o > 0; o >>= 1)
            v += __shfl_down_sync(0xFFFFFFFFu, v, o);

        if (t == 0) {
            // Decode scale: float32 bit pattern vs integer bit pattern.
            uint32_t u = scale_raw[0];
            float    f = __uint_as_float(u);
            float    scale;
            if (fabsf(f) >= 1e-30f && fabsf(f) < 1e30f) scale = f;
            else                                        scale = (float)(int)u;

            out[0] = v * scale / ((float)SEGN * (float)P);
            atomicExch(&g_counter, 0u);      // reset for next replay
        }
    }
}

extern "C" void kernel_launch(void* const* d_in, const int* in_sizes, int n_in,
                              void* d_out, int out_size)
{
    const float*    x     = (const float*)d_in[0];
    const uint32_t* scale = (const uint32_t*)d_in[1];
    float*          out   = (float*)d_out;

    int P       = in_sizes[0] / (N_POINTS * 2);     // 16384
    int nblocks = P / ROWS_PER_BLOCK;               // 2048

    xing_kernel<<<nblocks, SEGN>>>(x, scale, out, P, nblocks);
}

// round 8
// speedup vs baseline: 1.1364x; 1.0189x over previous
#include <cuda_runtime.h>
#include <cstdint>

// Fixed geometry: x_list (P=16384, N=1024, 2) float32, scale scalar.
// segn = N/4 = 256 segments per row; segment i uses points 3i..3i+3.
#define N_POINTS        1024
#define SEGN            256
#define ROWS_PER_BLOCK  8
#define NSLOTS          32

__device__ float        g_slots[NSLOTS];   // zero-init at load; reset each launch
__device__ unsigned int g_counter = 0;

// Crossing term for one segment given its 4 points.
__device__ __forceinline__ float seg_term(float2 p0, float2 p1, float2 p2, float2 p3)
{
    const float v1x = p1.x - p0.x, v1y = p1.y - p0.y;
    const float v2x = p2.x - p1.x, v2y = p2.y - p1.y;
    const float v3x = p3.x - p2.x, v3y = p3.y - p2.y;

    // direct = (s12 >= 0) depends only on sign of cross(v1,v2):
    // the positive norm product cannot flip the sign.
    const float c12 = v1x * v2y - v1y * v2x;
    const float c13 = v1x * v3y - v1y * v3x;

    const float n2   = (v1x * v1x + v1y * v1y) * (v3x * v3x + v3y * v3y);
    const float sina = c13 * rsqrtf(n2);

    return (c12 >= 0.0f) ? fmaxf(-sina, 0.0f) : fmaxf(sina, 0.0f);
}

__global__ void __launch_bounds__(SEGN, 8) xing_kernel(
    const float* __restrict__ x,
    const uint32_t* __restrict__ scale_raw,
    float* __restrict__ out, int P, int nblocks)
{
    const int t = threadIdx.x;               // segment index 0..255

    // Segment t starts at point 3t within each row.
    const float2* __restrict__ base =
        reinterpret_cast<const float2*>(x)
        + (size_t)blockIdx.x * ROWS_PER_BLOCK * N_POINTS + 3 * t;

    float acc = 0.0f;

    #pragma unroll
    for (int r = 0; r < ROWS_PER_BLOCK; r++) {
        const float2* p = base + (size_t)r * N_POINTS;
        const float2 p0 = __ldg(p + 0);
        const float2 p1 = __ldg(p + 1);
        const float2 p2 = __ldg(p + 2);
        const float2 p3 = __ldg(p + 3);
        acc += seg_term(p0, p1, p2, p3);
    }

    // ---- block reduce ----
    #pragma unroll
    for (int o = 16; o > 0; o >>= 1)
        acc += __shfl_down_sync(0xFFFFFFFFu, acc, o);

    __shared__ float s[SEGN / 32];
    if ((t & 31) == 0) s[t >> 5] = acc;
    __syncthreads();

    // Thread 0 only: accumulate into spread slots, detect last block, finalize.
    // Other threads (and other blocks) exit immediately — no extra barrier.
    if (t == 0) {
        float bs = 0.0f;
        #pragma unroll
        for (int i = 0; i < SEGN / 32; i++) bs += s[i];

        // 32 distinct L2 addresses, ~64 adds each, spread over the kernel
        // lifetime -> negligible atomic contention.
        atomicAdd(&g_slots[blockIdx.x & (NSLOTS - 1)], bs);
        __threadfence();
        unsigned int done = atomicAdd(&g_counter, 1u);

        if (done == (unsigned int)(nblocks - 1)) {
            // Last block: fold the 32 slots (32 independent loads, one
            // latency exposure) and reset state for the next graph replay.
            float v[NSLOTS];
            #pragma unroll
            for (int i = 0; i < NSLOTS; i++) v[i] = __ldcg(&g_slots[i]);

            float total = 0.0f;
            #pragma unroll
            for (int i = 0; i < NSLOTS; i++) {
                total += v[i];
                g_slots[i] = 0.0f;
            }

            // Decode scale: float32 bit pattern vs integer bit pattern.
            uint32_t u = scale_raw[0];
            float    f = __uint_as_float(u);
            float    scale;
            if (fabsf(f) >= 1e-30f && fabsf(f) < 1e30f) scale = f;
            else                                        scale = (float)(int)u;

            out[0] = total * scale / ((float)SEGN * (float)P);
            atomicExch(&g_counter, 0u);       // reset for next replay
        }
    }
}

extern "C" void kernel_launch(void* const* d_in, const int* in_sizes, int n_in,
                              void* d_out, int out_size)
{
    const float*    x     = (const float*)d_in[0];
    const uint32_t* scale = (const uint32_t*)d_in[1];
    float*          out   = (float*)d_out;

    int P       = in_sizes[0] / (N_POINTS * 2);     // 16384
    int nblocks = P / ROWS_PER_BLOCK;               // 2048

    xing_kernel<<<nblocks, SEGN>>>(x, scale, out, P, nblocks);
}